// round 2
// baseline (speedup 1.0000x reference)
#include <cuda_runtime.h>
#include <cstdint>
#include <cstddef>

#define NN 1023
#define DD 1024
#define BB 4
#define TT 8192
#define SST 44   // padded smem row stride (floats): float4-aligned + conflict-free frag loads

__device__ __align__(16) float g_states[BB * NN * DD];   // node states, fp32, ~16.8 MB
__device__ __align__(16) float g_mixture[BB * DD];

// ---------------------------------------------------------------------------
// 1. Leaves: g_states[b, 511+l, :] = mean over 8 timesteps of x[b, 8l.., :]
//    Only leaves 0..511 are used by the reference (valid = 512).
// ---------------------------------------------------------------------------
__global__ void __launch_bounds__(256) leaves_kernel(const float* __restrict__ x) {
    int blk = blockIdx.x;            // 0..2047 = (b, l)
    int b = blk >> 9;
    int l = blk & 511;
    int d4 = threadIdx.x;            // one float4 per thread (256*4 = 1024)
    const float4* xp = reinterpret_cast<const float4*>(x)
                       + ((size_t)(b * TT + l * 8)) * 256 + d4;
    float sx = 0.f, sy = 0.f, sz = 0.f, sw = 0.f;
#pragma unroll
    for (int i = 0; i < 8; i++) {
        float4 v = xp[(size_t)i * 256];
        sx += v.x; sy += v.y; sz += v.z; sw += v.w;
    }
    float4 o;
    o.x = sx * 0.125f; o.y = sy * 0.125f; o.z = sz * 0.125f; o.w = sw * 0.125f;
    reinterpret_cast<float4*>(g_states)[((size_t)b * NN + 511 + l) * 256 + d4] = o;
}

// ---------------------------------------------------------------------------
// 2. Tree level GEMM (tf32 tensor cores):
//    For level L: nodes [ls, ls+NL). Children of node ls+j are nodes
//    2(ls+j)+1, 2(ls+j)+2 — consecutive — so A is a dense (NL x 2048) matrix
//    at g_states[b, 2*ls+1, :] with lda = 2048. B = W_proj (1024 x 2048),
//    both K-contiguous -> mma row.col.
//    Epilogue: C = proj > bt[L][d] ? proj : 0
// ---------------------------------------------------------------------------
__device__ __forceinline__ void mma_tf32(float c[4], const unsigned a[4], const unsigned b[2]) {
    asm volatile(
        "mma.sync.aligned.m16n8k8.row.col.f32.tf32.tf32.f32 "
        "{%0,%1,%2,%3}, {%4,%5,%6,%7}, {%8,%9}, {%0,%1,%2,%3};\n"
        : "+f"(c[0]), "+f"(c[1]), "+f"(c[2]), "+f"(c[3])
        : "r"(a[0]), "r"(a[1]), "r"(a[2]), "r"(a[3]),
          "r"(b[0]), "r"(b[1]));
}

__global__ void __launch_bounds__(128) tree_gemm_kernel(const float* __restrict__ W,
                                                        const float* __restrict__ bt,
                                                        int level, int level_start, int NL) {
    int b  = blockIdx.z;
    int m0 = blockIdx.x * 64;
    int n0 = blockIdx.y * 64;
    const float* A  = g_states + ((size_t)b * NN + (2 * level_start + 1)) * DD;  // lda 2048
    float*       C  = g_states + ((size_t)b * NN + level_start) * DD;            // ldc 1024
    const float* Wt = W + (size_t)n0 * 2048;

    __shared__ float As[64 * SST];
    __shared__ float Bs[64 * SST];

    int tid = threadIdx.x;
    int warp = tid >> 5, lane = tid & 31;
    int wm = warp >> 1, wn = warp & 1;        // 2x2 warp grid, 32x32 per warp
    int g  = lane >> 2, t4 = lane & 3;

    float acc[2][4][4];
#pragma unroll
    for (int i = 0; i < 2; i++)
#pragma unroll
        for (int j = 0; j < 4; j++)
#pragma unroll
            for (int k = 0; k < 4; k++) acc[i][j][k] = 0.f;

    for (int k0 = 0; k0 < 2048; k0 += 32) {
        // stage 64x32 A tile (zero-padded past NL) and 64x32 W tile
#pragma unroll
        for (int i = tid; i < 512; i += 128) {
            int r = i >> 3, c = i & 7;
            float4 va = make_float4(0.f, 0.f, 0.f, 0.f);
            if (m0 + r < NL)
                va = *reinterpret_cast<const float4*>(A + (size_t)(m0 + r) * 2048 + k0 + c * 4);
            *reinterpret_cast<float4*>(&As[r * SST + c * 4]) = va;
            float4 vb = *reinterpret_cast<const float4*>(Wt + (size_t)r * 2048 + k0 + c * 4);
            *reinterpret_cast<float4*>(&Bs[r * SST + c * 4]) = vb;
        }
        __syncthreads();

#pragma unroll
        for (int kk = 0; kk < 32; kk += 8) {
            unsigned a[2][4], bf[4][2];
#pragma unroll
            for (int i = 0; i < 2; i++) {
                int rb = (wm * 32 + i * 16 + g) * SST + kk + t4;
                a[i][0] = __float_as_uint(As[rb]);
                a[i][1] = __float_as_uint(As[rb + 8 * SST]);
                a[i][2] = __float_as_uint(As[rb + 4]);
                a[i][3] = __float_as_uint(As[rb + 8 * SST + 4]);
            }
#pragma unroll
            for (int j = 0; j < 4; j++) {
                int rb = (wn * 32 + j * 8 + g) * SST + kk + t4;
                bf[j][0] = __float_as_uint(Bs[rb]);
                bf[j][1] = __float_as_uint(Bs[rb + 4]);
            }
#pragma unroll
            for (int i = 0; i < 2; i++)
#pragma unroll
                for (int j = 0; j < 4; j++)
                    mma_tf32(acc[i][j], a[i], bf[j]);
        }
        __syncthreads();
    }

    // epilogue: spike threshold, store
    const float* btL = bt + level * DD;
#pragma unroll
    for (int i = 0; i < 2; i++) {
        int row0 = m0 + wm * 32 + i * 16 + g;
#pragma unroll
        for (int j = 0; j < 4; j++) {
            int col = n0 + wn * 32 + j * 8 + t4 * 2;
            float thr0 = btL[col], thr1 = btL[col + 1];
            if (row0 < NL) {
                float v0 = acc[i][j][0], v1 = acc[i][j][1];
                C[(size_t)row0 * DD + col]     = v0 > thr0 ? v0 : 0.f;
                C[(size_t)row0 * DD + col + 1] = v1 > thr1 ? v1 : 0.f;
            }
            if (row0 + 8 < NL) {
                float v2 = acc[i][j][2], v3 = acc[i][j][3];
                C[(size_t)(row0 + 8) * DD + col]     = v2 > thr0 ? v2 : 0.f;
                C[(size_t)(row0 + 8) * DD + col + 1] = v3 > thr1 ? v3 : 0.f;
            }
        }
    }
}

// ---------------------------------------------------------------------------
// 3. Mixture: softmax over nodes (per d) dotted with node states.
//    |node_weights| < ~0.15 so exp() needs no max-subtraction (identical math).
// ---------------------------------------------------------------------------
__global__ void __launch_bounds__(512) mixture_kernel(const float* __restrict__ nw) {
    int ld = threadIdx.x & 31;
    int ln = threadIdx.x >> 5;        // 0..15 node-lanes
    int d  = blockIdx.x * 32 + ld;    // grid 32 -> d in [0,1024)
    float Z = 0.f, a0 = 0.f, a1 = 0.f, a2 = 0.f, a3 = 0.f;
    for (int n = ln; n < NN; n += 16) {
        float e = __expf(nw[n * DD + d]);
        Z += e;
        a0 += e * g_states[((size_t)0 * NN + n) * DD + d];
        a1 += e * g_states[((size_t)1 * NN + n) * DD + d];
        a2 += e * g_states[((size_t)2 * NN + n) * DD + d];
        a3 += e * g_states[((size_t)3 * NN + n) * DD + d];
    }
    __shared__ float red[5][16][32];
    red[0][ln][ld] = Z;  red[1][ln][ld] = a0; red[2][ln][ld] = a1;
    red[3][ln][ld] = a2; red[4][ln][ld] = a3;
    __syncthreads();
    if (ln == 0) {
        float z = 0.f, b0 = 0.f, b1 = 0.f, b2 = 0.f, b3 = 0.f;
#pragma unroll
        for (int i = 0; i < 16; i++) {
            z  += red[0][i][ld]; b0 += red[1][i][ld]; b1 += red[2][i][ld];
            b2 += red[3][i][ld]; b3 += red[4][i][ld];
        }
        float inv = 1.f / z;
        g_mixture[0 * DD + d] = b0 * inv;
        g_mixture[1 * DD + d] = b1 * inv;
        g_mixture[2 * DD + d] = b2 * inv;
        g_mixture[3 * DD + d] = b3 * inv;
    }
}

// ---------------------------------------------------------------------------
// 4. Final: out = RMSNorm(x + mixture[b]) * rms_w.  8 rows per block so the
//    mixture / rms_w vectors are read once per 8 output rows (smem).
// ---------------------------------------------------------------------------
__global__ void __launch_bounds__(256) final_kernel(const float* __restrict__ x,
                                                    const float* __restrict__ rms_w,
                                                    float* __restrict__ out) {
    int blk = blockIdx.x;                 // 4096 blocks
    int b  = blk >> 10;
    int t0 = (blk & 1023) * 8;
    int tid = threadIdx.x;
    int lane = tid & 31, warp = tid >> 5;

    __shared__ float4 smix[256];
    __shared__ float4 srw[256];
    __shared__ float  sred[8];

    smix[tid] = reinterpret_cast<const float4*>(g_mixture + b * DD)[tid];
    srw[tid]  = reinterpret_cast<const float4*>(rms_w)[tid];
    __syncthreads();
    float4 mix = smix[tid], rw = srw[tid];

    const float4* xb = reinterpret_cast<const float4*>(x)   + ((size_t)(b * TT + t0)) * 256;
    float4*       ob = reinterpret_cast<float4*>(out)       + ((size_t)(b * TT + t0)) * 256;

    for (int r = 0; r < 8; r++) {
        float4 v = xb[(size_t)r * 256 + tid];
        v.x += mix.x; v.y += mix.y; v.z += mix.z; v.w += mix.w;
        float ss = v.x * v.x + v.y * v.y + v.z * v.z + v.w * v.w;
#pragma unroll
        for (int o = 16; o > 0; o >>= 1) ss += __shfl_xor_sync(0xffffffffu, ss, o);
        __syncthreads();              // sred reuse guard across iterations
        if (lane == 0) sred[warp] = ss;
        __syncthreads();
        float tot = 0.f;
#pragma unroll
        for (int i = 0; i < 8; i++) tot += sred[i];
        float inv = rsqrtf(tot * (1.0f / 1024.0f) + 1.1920929e-7f);
        float4 o4;
        o4.x = v.x * rw.x * inv; o4.y = v.y * rw.y * inv;
        o4.z = v.z * rw.z * inv; o4.w = v.w * rw.w * inv;
        ob[(size_t)r * 256 + tid] = o4;
    }
}

// ---------------------------------------------------------------------------
// launch: leaves -> levels 8..0 -> mixture -> final   (12 launches, all on the
// capture stream, no syncs, no allocations)
// ---------------------------------------------------------------------------
extern "C" void kernel_launch(void* const* d_in, const int* in_sizes, int n_in,
                              void* d_out, int out_size) {
    const float* x     = (const float*)d_in[0];
    const float* W     = (const float*)d_in[1];
    const float* nw    = (const float*)d_in[2];
    const float* bt    = (const float*)d_in[3];
    // d_in[4] = as_w: multiplied by 0.0 in the reference -> unused
    const float* rms_w = (const float*)d_in[5];
    float* out = (float*)d_out;

    leaves_kernel<<<2048, 256>>>(x);

    for (int lvl = 8; lvl >= 0; --lvl) {
        int NL = 1 << lvl;
        int ls = NL - 1;
        dim3 grid((NL + 63) / 64, 16, 4);
        tree_gemm_kernel<<<grid, 128>>>(W, bt, lvl, ls, NL);
    }

    mixture_kernel<<<32, 512>>>(nw);
    final_kernel<<<4096, 256>>>(x, rms_w, out);
}

// round 3
// speedup vs baseline: 2.5838x; 2.5838x over previous
#include <cuda_runtime.h>
#include <cstdint>
#include <cstddef>

#define NN 1023
#define DD 1024
#define BB 4
#define TT 8192
#define SST 44   // padded smem row stride (floats): float4-aligned + conflict-free frag loads

__device__ __align__(16) float g_states[BB * NN * DD];     // node states, fp32, ~16.8 MB
__device__ __align__(16) float g_partial[1024 * 1024];     // split-K partials, 4 MB (S*Mtot <= 1024)
__device__ __align__(16) float g_mixture[BB * DD];
__device__ __align__(16) float g_mixpart[8][5][DD];        // [split][Z,a0..a3][d]

// ---------------------------------------------------------------------------
// 1. Leaves: g_states[b, 511+l, :] = mean over 8 timesteps of x[b, 8l.., :]
// ---------------------------------------------------------------------------
__global__ void __launch_bounds__(256) leaves_kernel(const float* __restrict__ x) {
    int blk = blockIdx.x;            // 0..2047 = (b, l)
    int b = blk >> 9;
    int l = blk & 511;
    int d4 = threadIdx.x;
    const float4* xp = reinterpret_cast<const float4*>(x)
                       + ((size_t)(b * TT + l * 8)) * 256 + d4;
    float sx = 0.f, sy = 0.f, sz = 0.f, sw = 0.f;
#pragma unroll
    for (int i = 0; i < 8; i++) {
        float4 v = xp[(size_t)i * 256];
        sx += v.x; sy += v.y; sz += v.z; sw += v.w;
    }
    float4 o;
    o.x = sx * 0.125f; o.y = sy * 0.125f; o.z = sz * 0.125f; o.w = sw * 0.125f;
    reinterpret_cast<float4*>(g_states)[((size_t)b * NN + 511 + l) * 256 + d4] = o;
}

// ---------------------------------------------------------------------------
// 2. Tree level GEMM, tf32 tensor cores, batch folded into M, split-K,
//    cp.async double-buffered staging.
//    Level L: M = 4*NL rows (row r -> b = r>>L, node j = r&(NL-1)),
//    A row = g_states[b, 2*ls+1+2*j, :] (2048 contiguous floats),
//    B = W_proj[n, :] (K-contiguous) -> mma row.col.
//    S==1: epilogue applies spike threshold directly into g_states.
//    S>1 : writes raw partials; reduce_spike sums + thresholds.
// ---------------------------------------------------------------------------
__device__ __forceinline__ void mma_tf32(float c[4], const unsigned a[4], const unsigned b[2]) {
    asm volatile(
        "mma.sync.aligned.m16n8k8.row.col.f32.tf32.tf32.f32 "
        "{%0,%1,%2,%3}, {%4,%5,%6,%7}, {%8,%9}, {%0,%1,%2,%3};\n"
        : "+f"(c[0]), "+f"(c[1]), "+f"(c[2]), "+f"(c[3])
        : "r"(a[0]), "r"(a[1]), "r"(a[2]), "r"(a[3]),
          "r"(b[0]), "r"(b[1]));
}

__device__ __forceinline__ unsigned smem_u32(const void* p) {
    return (unsigned)__cvta_generic_to_shared(p);
}

__global__ void __launch_bounds__(128) tree_gemm2_kernel(const float* __restrict__ W,
                                                         const float* __restrict__ bt,
                                                         int level, int ls, int NL,
                                                         int S, int Kslab) {
    int split = blockIdx.z;
    int m0 = blockIdx.x * 64;
    int n0 = blockIdx.y * 64;
    int Mtot = NL * 4;
    int kbeg = split * Kslab;
    int iters = Kslab >> 5;

    __shared__ float As[2][64 * SST];
    __shared__ float Bs[2][64 * SST];

    int tid = threadIdx.x;
    int warp = tid >> 5, lane = tid & 31;
    int wm = warp >> 1, wn = warp & 1;
    int g = lane >> 2, t4 = lane & 3;

    float acc[2][4][4];
#pragma unroll
    for (int i = 0; i < 2; i++)
#pragma unroll
        for (int j = 0; j < 4; j++)
#pragma unroll
            for (int k = 0; k < 4; k++) acc[i][j][k] = 0.f;

    // staging: 128 threads x 4 float4 per tile (64 rows x 8 float4-cols)
    // A row base (global floats) precomputable per (r); rows beyond Mtot zero-filled.
#define STAGE(buf, kg)                                                               \
    {                                                                                \
        _Pragma("unroll")                                                            \
        for (int q = 0; q < 4; q++) {                                                \
            int i = q * 128 + tid;                                                   \
            int r = i >> 3, c = i & 7;                                               \
            unsigned sa = smem_u32(&As[buf][r * SST + c * 4]);                       \
            int rg = m0 + r;                                                         \
            const float* pa = W;                                                     \
            int sz = 0;                                                              \
            if (rg < Mtot) {                                                         \
                int bb = rg >> level;                                                \
                int jj = rg & (NL - 1);                                              \
                pa = g_states + ((size_t)bb * NN + (2 * ls + 1) + 2 * jj) * DD       \
                     + (kg) + c * 4;                                                 \
                sz = 16;                                                             \
            }                                                                        \
            asm volatile("cp.async.cg.shared.global [%0], [%1], 16, %2;\n"           \
                         :: "r"(sa), "l"(pa), "r"(sz));                              \
            unsigned sb = smem_u32(&Bs[buf][r * SST + c * 4]);                       \
            const float* pb = W + (size_t)(n0 + r) * 2048 + (kg) + c * 4;            \
            asm volatile("cp.async.cg.shared.global [%0], [%1], 16;\n"               \
                         :: "r"(sb), "l"(pb));                                       \
        }                                                                            \
        asm volatile("cp.async.commit_group;\n");                                    \
    }

    STAGE(0, kbeg);

    for (int it = 0; it < iters; ++it) {
        int cur = it & 1;
        if (it + 1 < iters) {
            STAGE(cur ^ 1, kbeg + (it + 1) * 32);
            asm volatile("cp.async.wait_group 1;\n");
        } else {
            asm volatile("cp.async.wait_group 0;\n");
        }
        __syncthreads();

#pragma unroll
        for (int kk = 0; kk < 32; kk += 8) {
            unsigned a[2][4], bf[4][2];
#pragma unroll
            for (int i = 0; i < 2; i++) {
                int rb = (wm * 32 + i * 16 + g) * SST + kk + t4;
                a[i][0] = __float_as_uint(As[cur][rb]);
                a[i][1] = __float_as_uint(As[cur][rb + 8 * SST]);
                a[i][2] = __float_as_uint(As[cur][rb + 4]);
                a[i][3] = __float_as_uint(As[cur][rb + 8 * SST + 4]);
            }
#pragma unroll
            for (int j = 0; j < 4; j++) {
                int rb = (wn * 32 + j * 8 + g) * SST + kk + t4;
                bf[j][0] = __float_as_uint(Bs[cur][rb]);
                bf[j][1] = __float_as_uint(Bs[cur][rb + 4]);
            }
#pragma unroll
            for (int i = 0; i < 2; i++)
#pragma unroll
                for (int j = 0; j < 4; j++)
                    mma_tf32(acc[i][j], a[i], bf[j]);
        }
        __syncthreads();
    }
#undef STAGE

    // epilogue
    if (S == 1) {
        const float* btL = bt + level * DD;
#pragma unroll
        for (int i = 0; i < 2; i++) {
            int rg = m0 + wm * 32 + i * 16 + g;
#pragma unroll
            for (int j = 0; j < 4; j++) {
                int col = n0 + wn * 32 + j * 8 + t4 * 2;
                float thr0 = btL[col], thr1 = btL[col + 1];
                if (rg < Mtot) {
                    int bb = rg >> level, jj = rg & (NL - 1);
                    float* Crow = g_states + ((size_t)bb * NN + ls + jj) * DD;
                    float v0 = acc[i][j][0], v1 = acc[i][j][1];
                    Crow[col]     = v0 > thr0 ? v0 : 0.f;
                    Crow[col + 1] = v1 > thr1 ? v1 : 0.f;
                }
                int rg8 = rg + 8;
                if (rg8 < Mtot) {
                    int bb = rg8 >> level, jj = rg8 & (NL - 1);
                    float* Crow = g_states + ((size_t)bb * NN + ls + jj) * DD;
                    float v2 = acc[i][j][2], v3 = acc[i][j][3];
                    Crow[col]     = v2 > thr0 ? v2 : 0.f;
                    Crow[col + 1] = v3 > thr1 ? v3 : 0.f;
                }
            }
        }
    } else {
        float* P = g_partial + (size_t)split * Mtot * DD;
#pragma unroll
        for (int i = 0; i < 2; i++) {
            int rg = m0 + wm * 32 + i * 16 + g;
#pragma unroll
            for (int j = 0; j < 4; j++) {
                int col = n0 + wn * 32 + j * 8 + t4 * 2;
                if (rg < Mtot) {
                    P[(size_t)rg * DD + col]     = acc[i][j][0];
                    P[(size_t)rg * DD + col + 1] = acc[i][j][1];
                }
                if (rg + 8 < Mtot) {
                    P[(size_t)(rg + 8) * DD + col]     = acc[i][j][2];
                    P[(size_t)(rg + 8) * DD + col + 1] = acc[i][j][3];
                }
            }
        }
    }
}

// split-K reduction + spike threshold -> g_states
__global__ void __launch_bounds__(256) reduce_spike_kernel(const float* __restrict__ bt,
                                                           int level, int ls, int NL, int S) {
    int Mtot = NL * 4;
    int idx = blockIdx.x * 256 + threadIdx.x;
    if (idx >= Mtot * DD) return;
    int r = idx >> 10, d = idx & (DD - 1);
    size_t stride = (size_t)Mtot * DD;
    float s = 0.f;
    for (int k = 0; k < S; k++) s += g_partial[(size_t)k * stride + idx];
    int bb = r >> level, jj = r & (NL - 1);
    float thr = bt[level * DD + d];
    g_states[((size_t)bb * NN + ls + jj) * DD + d] = s > thr ? s : 0.f;
}

// ---------------------------------------------------------------------------
// 3. Mixture, two-stage: stage1 over node splits, stage2 combine + normalize.
//    |node_weights| small -> exp without max-subtraction (identical math).
// ---------------------------------------------------------------------------
__global__ void __launch_bounds__(512) mixture1_kernel(const float* __restrict__ nw) {
    int ld = threadIdx.x & 31;
    int ln = threadIdx.x >> 5;            // 0..15
    int d  = blockIdx.x * 32 + ld;
    int sp = blockIdx.y;                  // 0..7, nodes [sp*128, sp*128+128) ∩ [0,1023)
    int nend = sp * 128 + 128;
    if (nend > NN) nend = NN;
    float Z = 0.f, a0 = 0.f, a1 = 0.f, a2 = 0.f, a3 = 0.f;
    for (int n = sp * 128 + ln; n < nend; n += 16) {
        float e = __expf(nw[n * DD + d]);
        Z += e;
        a0 += e * g_states[((size_t)0 * NN + n) * DD + d];
        a1 += e * g_states[((size_t)1 * NN + n) * DD + d];
        a2 += e * g_states[((size_t)2 * NN + n) * DD + d];
        a3 += e * g_states[((size_t)3 * NN + n) * DD + d];
    }
    __shared__ float red[5][16][32];
    red[0][ln][ld] = Z;  red[1][ln][ld] = a0; red[2][ln][ld] = a1;
    red[3][ln][ld] = a2; red[4][ln][ld] = a3;
    __syncthreads();
    if (ln == 0) {
        float v[5];
#pragma unroll
        for (int k = 0; k < 5; k++) {
            float s = 0.f;
#pragma unroll
            for (int i = 0; i < 16; i++) s += red[k][i][ld];
            v[k] = s;
        }
#pragma unroll
        for (int k = 0; k < 5; k++) g_mixpart[sp][k][d] = v[k];
    }
}

__global__ void __launch_bounds__(256) mixture2_kernel() {
    int d = blockIdx.x * 256 + threadIdx.x;   // grid 4
    float Z = 0.f, a0 = 0.f, a1 = 0.f, a2 = 0.f, a3 = 0.f;
#pragma unroll
    for (int sp = 0; sp < 8; sp++) {
        Z  += g_mixpart[sp][0][d];
        a0 += g_mixpart[sp][1][d];
        a1 += g_mixpart[sp][2][d];
        a2 += g_mixpart[sp][3][d];
        a3 += g_mixpart[sp][4][d];
    }
    float inv = 1.f / Z;
    g_mixture[0 * DD + d] = a0 * inv;
    g_mixture[1 * DD + d] = a1 * inv;
    g_mixture[2 * DD + d] = a2 * inv;
    g_mixture[3 * DD + d] = a3 * inv;
}

// ---------------------------------------------------------------------------
// 4. Final: out = RMSNorm(x + mixture[b]) * rms_w, 8 rows per block.
// ---------------------------------------------------------------------------
__global__ void __launch_bounds__(256) final_kernel(const float* __restrict__ x,
                                                    const float* __restrict__ rms_w,
                                                    float* __restrict__ out) {
    int blk = blockIdx.x;                 // 4096 blocks
    int b  = blk >> 10;
    int t0 = (blk & 1023) * 8;
    int tid = threadIdx.x;
    int lane = tid & 31, warp = tid >> 5;

    __shared__ float4 smix[256];
    __shared__ float4 srw[256];
    __shared__ float  sred[8];

    smix[tid] = reinterpret_cast<const float4*>(g_mixture + b * DD)[tid];
    srw[tid]  = reinterpret_cast<const float4*>(rms_w)[tid];
    __syncthreads();
    float4 mix = smix[tid], rw = srw[tid];

    const float4* xb = reinterpret_cast<const float4*>(x)   + ((size_t)(b * TT + t0)) * 256;
    float4*       ob = reinterpret_cast<float4*>(out)       + ((size_t)(b * TT + t0)) * 256;

    for (int r = 0; r < 8; r++) {
        float4 v = xb[(size_t)r * 256 + tid];
        v.x += mix.x; v.y += mix.y; v.z += mix.z; v.w += mix.w;
        float ss = v.x * v.x + v.y * v.y + v.z * v.z + v.w * v.w;
#pragma unroll
        for (int o = 16; o > 0; o >>= 1) ss += __shfl_xor_sync(0xffffffffu, ss, o);
        __syncthreads();
        if (lane == 0) sred[warp] = ss;
        __syncthreads();
        float tot = 0.f;
#pragma unroll
        for (int i = 0; i < 8; i++) tot += sred[i];
        float inv = rsqrtf(tot * (1.0f / 1024.0f) + 1.1920929e-7f);
        float4 o4;
        o4.x = v.x * rw.x * inv; o4.y = v.y * rw.y * inv;
        o4.z = v.z * rw.z * inv; o4.w = v.w * rw.w * inv;
        ob[(size_t)r * 256 + tid] = o4;
    }
}

// ---------------------------------------------------------------------------
// launch
// ---------------------------------------------------------------------------
extern "C" void kernel_launch(void* const* d_in, const int* in_sizes, int n_in,
                              void* d_out, int out_size) {
    const float* x     = (const float*)d_in[0];
    const float* W     = (const float*)d_in[1];
    const float* nw    = (const float*)d_in[2];
    const float* bt    = (const float*)d_in[3];
    const float* rms_w = (const float*)d_in[5];   // as_w (d_in[4]) unused (×0.0)
    float* out = (float*)d_out;

    leaves_kernel<<<2048, 256>>>(x);

    // level 8: M = 1024, no split, fused epilogue
    tree_gemm2_kernel<<<dim3(16, 16, 1), 128>>>(W, bt, 8, 255, 256, 1, 2048);

    for (int lvl = 7; lvl >= 0; --lvl) {
        int NL = 1 << lvl;
        int ls = NL - 1;
        int Mtot = 4 * NL;
        int S = 1024 / Mtot; if (S > 16) S = 16;
        int Kslab = 2048 / S;
        dim3 grid((Mtot + 63) / 64, 16, S);
        tree_gemm2_kernel<<<grid, 128>>>(W, bt, lvl, ls, NL, S, Kslab);
        reduce_spike_kernel<<<(Mtot * DD + 255) / 256, 256>>>(bt, lvl, ls, NL, S);
    }

    mixture1_kernel<<<dim3(32, 8), 512>>>(nw);
    mixture2_kernel<<<4, 256>>>();
    final_kernel<<<4096, 256>>>(x, rms_w, out);
}

// round 4
// speedup vs baseline: 2.6942x; 1.0427x over previous
#include <cuda_runtime.h>
#include <cstdint>
#include <cstddef>

#define NN 1023
#define DD 1024
#define BB 4
#define TT 8192
#define SST 44   // padded smem row stride (floats): float4-aligned + conflict-free frag loads

__device__ __align__(16) float g_states[BB * NN * DD];     // node states, fp32 (raw proj for internal nodes)
__device__ __align__(16) float g_mixture[BB * DD];
__device__ __align__(16) float g_mixpart[8][5][DD];        // [split][Z,a0..a3][d]

// ---------------------------------------------------------------------------
// 0. Zero internal nodes 0..254 (atomic split-K targets) for all batches.
//    4 * 255 * 1024 floats = 261120 float4.
// ---------------------------------------------------------------------------
__global__ void __launch_bounds__(256) zero_internal_kernel() {
    int i = blockIdx.x * 256 + threadIdx.x;
    if (i < 261120) {
        int b = i / 65280;          // 255*1024/4 float4 per batch
        int r = i - b * 65280;
        reinterpret_cast<float4*>(g_states + (size_t)b * NN * DD)[r] =
            make_float4(0.f, 0.f, 0.f, 0.f);
    }
}

// ---------------------------------------------------------------------------
// 1. Leaves: g_states[b, 511+l, :] = mean over 8 timesteps of x[b, 8l.., :]
// ---------------------------------------------------------------------------
__global__ void __launch_bounds__(256) leaves_kernel(const float* __restrict__ x) {
    int blk = blockIdx.x;            // 0..2047 = (b, l)
    int b = blk >> 9;
    int l = blk & 511;
    int d4 = threadIdx.x;
    const float4* xp = reinterpret_cast<const float4*>(x)
                       + ((size_t)(b * TT + l * 8)) * 256 + d4;
    float sx = 0.f, sy = 0.f, sz = 0.f, sw = 0.f;
#pragma unroll
    for (int i = 0; i < 8; i++) {
        float4 v = xp[(size_t)i * 256];
        sx += v.x; sy += v.y; sz += v.z; sw += v.w;
    }
    float4 o;
    o.x = sx * 0.125f; o.y = sy * 0.125f; o.z = sz * 0.125f; o.w = sw * 0.125f;
    reinterpret_cast<float4*>(g_states)[((size_t)b * NN + 511 + l) * 256 + d4] = o;
}

// ---------------------------------------------------------------------------
// 2. Tree level GEMM, tf32 mma, batch folded into M, split-K via atomicAdd,
//    cp.async double-buffered staging, LAZY spike threshold:
//    g_states holds RAW proj sums; the threshold for the children (level L+1,
//    bt[L+1][k&1023]) is applied when loading A fragments (btc != null).
//    Level 8 (A = leaves) passes btc = null -> -FLT_MAX sentinel thresholds.
//    S==1: direct raw store.  S>1: atomicAdd of raw partials (needs zero-init).
// ---------------------------------------------------------------------------
__device__ __forceinline__ void mma_tf32(float c[4], const unsigned a[4], const unsigned b[2]) {
    asm volatile(
        "mma.sync.aligned.m16n8k8.row.col.f32.tf32.tf32.f32 "
        "{%0,%1,%2,%3}, {%4,%5,%6,%7}, {%8,%9}, {%0,%1,%2,%3};\n"
        : "+f"(c[0]), "+f"(c[1]), "+f"(c[2]), "+f"(c[3])
        : "r"(a[0]), "r"(a[1]), "r"(a[2]), "r"(a[3]),
          "r"(b[0]), "r"(b[1]));
}

__device__ __forceinline__ unsigned smem_u32(const void* p) {
    return (unsigned)__cvta_generic_to_shared(p);
}

__global__ void __launch_bounds__(128) tree_gemm2_kernel(const float* __restrict__ W,
                                                         const float* __restrict__ btc,
                                                         int level, int ls, int NL,
                                                         int S, int Kslab) {
    int split = blockIdx.z;
    int m0 = blockIdx.x * 64;
    int n0 = blockIdx.y * 64;
    int Mtot = NL * 4;
    int kbeg = split * Kslab;
    int iters = Kslab >> 5;

    __shared__ float As[2][64 * SST];
    __shared__ float Bs[2][64 * SST];
    __shared__ float tb[2][32];          // child thresholds for this K-slab chunk

    int tid = threadIdx.x;
    int warp = tid >> 5, lane = tid & 31;
    int wm = warp >> 1, wn = warp & 1;
    int g = lane >> 2, t4 = lane & 3;

    float acc[2][4][4];
#pragma unroll
    for (int i = 0; i < 2; i++)
#pragma unroll
        for (int j = 0; j < 4; j++)
#pragma unroll
            for (int k = 0; k < 4; k++) acc[i][j][k] = 0.f;

#define STAGE(buf, kg)                                                               \
    {                                                                                \
        _Pragma("unroll")                                                            \
        for (int q = 0; q < 4; q++) {                                                \
            int i = q * 128 + tid;                                                   \
            int r = i >> 3, c = i & 7;                                               \
            unsigned sa = smem_u32(&As[buf][r * SST + c * 4]);                       \
            int rg = m0 + r;                                                         \
            const float* pa = W;                                                     \
            int sz = 0;                                                              \
            if (rg < Mtot) {                                                         \
                int bb = rg >> level;                                                \
                int jj = rg & (NL - 1);                                              \
                pa = g_states + ((size_t)bb * NN + (2 * ls + 1) + 2 * jj) * DD       \
                     + (kg) + c * 4;                                                 \
                sz = 16;                                                             \
            }                                                                        \
            asm volatile("cp.async.cg.shared.global [%0], [%1], 16, %2;\n"           \
                         :: "r"(sa), "l"(pa), "r"(sz));                              \
            unsigned sb = smem_u32(&Bs[buf][r * SST + c * 4]);                       \
            const float* pb = W + (size_t)(n0 + r) * 2048 + (kg) + c * 4;            \
            asm volatile("cp.async.cg.shared.global [%0], [%1], 16;\n"               \
                         :: "r"(sb), "l"(pb));                                       \
        }                                                                            \
        if (tid < 8) {                                                               \
            if (btc) {                                                               \
                unsigned st = smem_u32(&tb[buf][tid * 4]);                           \
                const float* pt = btc + (((kg) & 1023) + tid * 4);                   \
                asm volatile("cp.async.ca.shared.global [%0], [%1], 16;\n"           \
                             :: "r"(st), "l"(pt));                                   \
            } else {                                                                 \
                *reinterpret_cast<float4*>(&tb[buf][tid * 4]) =                      \
                    make_float4(-3.4e38f, -3.4e38f, -3.4e38f, -3.4e38f);             \
            }                                                                        \
        }                                                                            \
        asm volatile("cp.async.commit_group;\n");                                    \
    }

    STAGE(0, kbeg);

    for (int it = 0; it < iters; ++it) {
        int cur = it & 1;
        if (it + 1 < iters) {
            STAGE(cur ^ 1, kbeg + (it + 1) * 32);
            asm volatile("cp.async.wait_group 1;\n");
        } else {
            asm volatile("cp.async.wait_group 0;\n");
        }
        __syncthreads();

#pragma unroll
        for (int kk = 0; kk < 32; kk += 8) {
            float thr_lo = tb[cur][kk + t4];
            float thr_hi = tb[cur][kk + t4 + 4];
            unsigned a[2][4], bf[4][2];
#pragma unroll
            for (int i = 0; i < 2; i++) {
                int rb = (wm * 32 + i * 16 + g) * SST + kk + t4;
                float f0 = As[cur][rb];
                float f1 = As[cur][rb + 8 * SST];
                float f2 = As[cur][rb + 4];
                float f3 = As[cur][rb + 8 * SST + 4];
                a[i][0] = __float_as_uint(f0 > thr_lo ? f0 : 0.f);
                a[i][1] = __float_as_uint(f1 > thr_lo ? f1 : 0.f);
                a[i][2] = __float_as_uint(f2 > thr_hi ? f2 : 0.f);
                a[i][3] = __float_as_uint(f3 > thr_hi ? f3 : 0.f);
            }
#pragma unroll
            for (int j = 0; j < 4; j++) {
                int rb = (wn * 32 + j * 8 + g) * SST + kk + t4;
                bf[j][0] = __float_as_uint(Bs[cur][rb]);
                bf[j][1] = __float_as_uint(Bs[cur][rb + 4]);
            }
#pragma unroll
            for (int i = 0; i < 2; i++)
#pragma unroll
                for (int j = 0; j < 4; j++)
                    mma_tf32(acc[i][j], a[i], bf[j]);
        }
        __syncthreads();
    }
#undef STAGE

    // epilogue: store RAW proj (threshold applied lazily by consumers)
    if (S == 1) {
#pragma unroll
        for (int i = 0; i < 2; i++) {
            int rg = m0 + wm * 32 + i * 16 + g;
#pragma unroll
            for (int j = 0; j < 4; j++) {
                int col = n0 + wn * 32 + j * 8 + t4 * 2;
                if (rg < Mtot) {
                    int bb = rg >> level, jj = rg & (NL - 1);
                    float* Crow = g_states + ((size_t)bb * NN + ls + jj) * DD;
                    Crow[col]     = acc[i][j][0];
                    Crow[col + 1] = acc[i][j][1];
                }
                int rg8 = rg + 8;
                if (rg8 < Mtot) {
                    int bb = rg8 >> level, jj = rg8 & (NL - 1);
                    float* Crow = g_states + ((size_t)bb * NN + ls + jj) * DD;
                    Crow[col]     = acc[i][j][2];
                    Crow[col + 1] = acc[i][j][3];
                }
            }
        }
    } else {
#pragma unroll
        for (int i = 0; i < 2; i++) {
            int rg = m0 + wm * 32 + i * 16 + g;
#pragma unroll
            for (int j = 0; j < 4; j++) {
                int col = n0 + wn * 32 + j * 8 + t4 * 2;
                if (rg < Mtot) {
                    int bb = rg >> level, jj = rg & (NL - 1);
                    float* Crow = g_states + ((size_t)bb * NN + ls + jj) * DD;
                    atomicAdd(&Crow[col],     acc[i][j][0]);
                    atomicAdd(&Crow[col + 1], acc[i][j][1]);
                }
                int rg8 = rg + 8;
                if (rg8 < Mtot) {
                    int bb = rg8 >> level, jj = rg8 & (NL - 1);
                    float* Crow = g_states + ((size_t)bb * NN + ls + jj) * DD;
                    atomicAdd(&Crow[col],     acc[i][j][2]);
                    atomicAdd(&Crow[col + 1], acc[i][j][3]);
                }
            }
        }
    }
}

// ---------------------------------------------------------------------------
// 3. Mixture, two-stage, with lazy spike threshold per node level.
//    node n level = floor(log2(n+1)); internal nodes (n<511) thresholded,
//    leaves (511..1022) raw.
// ---------------------------------------------------------------------------
__global__ void __launch_bounds__(512) mixture1_kernel(const float* __restrict__ nw,
                                                       const float* __restrict__ bt) {
    int ld = threadIdx.x & 31;
    int ln = threadIdx.x >> 5;            // 0..15
    int d  = blockIdx.x * 32 + ld;
    int sp = blockIdx.y;                  // nodes [sp*128, sp*128+128) ∩ [0,1023)
    int nend = sp * 128 + 128;
    if (nend > NN) nend = NN;
    float Z = 0.f, a0 = 0.f, a1 = 0.f, a2 = 0.f, a3 = 0.f;
    for (int n = sp * 128 + ln; n < nend; n += 16) {
        float e = __expf(nw[n * DD + d]);
        float v0 = g_states[((size_t)0 * NN + n) * DD + d];
        float v1 = g_states[((size_t)1 * NN + n) * DD + d];
        float v2 = g_states[((size_t)2 * NN + n) * DD + d];
        float v3 = g_states[((size_t)3 * NN + n) * DD + d];
        if (n < 511) {
            int lv = 31 - __clz(n + 1);
            float thr = bt[lv * DD + d];
            v0 = v0 > thr ? v0 : 0.f;
            v1 = v1 > thr ? v1 : 0.f;
            v2 = v2 > thr ? v2 : 0.f;
            v3 = v3 > thr ? v3 : 0.f;
        }
        Z += e;
        a0 += e * v0; a1 += e * v1; a2 += e * v2; a3 += e * v3;
    }
    __shared__ float red[5][16][32];
    red[0][ln][ld] = Z;  red[1][ln][ld] = a0; red[2][ln][ld] = a1;
    red[3][ln][ld] = a2; red[4][ln][ld] = a3;
    __syncthreads();
    if (ln == 0) {
        float v[5];
#pragma unroll
        for (int k = 0; k < 5; k++) {
            float s = 0.f;
#pragma unroll
            for (int i = 0; i < 16; i++) s += red[k][i][ld];
            v[k] = s;
        }
#pragma unroll
        for (int k = 0; k < 5; k++) g_mixpart[sp][k][d] = v[k];
    }
}

__global__ void __launch_bounds__(256) mixture2_kernel() {
    int d = blockIdx.x * 256 + threadIdx.x;   // grid 4
    float Z = 0.f, a0 = 0.f, a1 = 0.f, a2 = 0.f, a3 = 0.f;
#pragma unroll
    for (int sp = 0; sp < 8; sp++) {
        Z  += g_mixpart[sp][0][d];
        a0 += g_mixpart[sp][1][d];
        a1 += g_mixpart[sp][2][d];
        a2 += g_mixpart[sp][3][d];
        a3 += g_mixpart[sp][4][d];
    }
    float inv = 1.f / Z;
    g_mixture[0 * DD + d] = a0 * inv;
    g_mixture[1 * DD + d] = a1 * inv;
    g_mixture[2 * DD + d] = a2 * inv;
    g_mixture[3 * DD + d] = a3 * inv;
}

// ---------------------------------------------------------------------------
// 4. Final: out = RMSNorm(x + mixture[b]) * rms_w, 8 rows per block.
// ---------------------------------------------------------------------------
__global__ void __launch_bounds__(256) final_kernel(const float* __restrict__ x,
                                                    const float* __restrict__ rms_w,
                                                    float* __restrict__ out) {
    int blk = blockIdx.x;                 // 4096 blocks
    int b  = blk >> 10;
    int t0 = (blk & 1023) * 8;
    int tid = threadIdx.x;
    int lane = tid & 31, warp = tid >> 5;

    __shared__ float4 smix[256];
    __shared__ float4 srw[256];
    __shared__ float  sred[8];

    smix[tid] = reinterpret_cast<const float4*>(g_mixture + b * DD)[tid];
    srw[tid]  = reinterpret_cast<const float4*>(rms_w)[tid];
    __syncthreads();
    float4 mix = smix[tid], rw = srw[tid];

    const float4* xb = reinterpret_cast<const float4*>(x)   + ((size_t)(b * TT + t0)) * 256;
    float4*       ob = reinterpret_cast<float4*>(out)       + ((size_t)(b * TT + t0)) * 256;

    for (int r = 0; r < 8; r++) {
        float4 v = xb[(size_t)r * 256 + tid];
        v.x += mix.x; v.y += mix.y; v.z += mix.z; v.w += mix.w;
        float ss = v.x * v.x + v.y * v.y + v.z * v.z + v.w * v.w;
#pragma unroll
        for (int o = 16; o > 0; o >>= 1) ss += __shfl_xor_sync(0xffffffffu, ss, o);
        __syncthreads();
        if (lane == 0) sred[warp] = ss;
        __syncthreads();
        float tot = 0.f;
#pragma unroll
        for (int i = 0; i < 8; i++) tot += sred[i];
        float inv = rsqrtf(tot * (1.0f / 1024.0f) + 1.1920929e-7f);
        float4 o4;
        o4.x = v.x * rw.x * inv; o4.y = v.y * rw.y * inv;
        o4.z = v.z * rw.z * inv; o4.w = v.w * rw.w * inv;
        ob[(size_t)r * 256 + tid] = o4;
    }
}

// ---------------------------------------------------------------------------
// launch: zero -> leaves -> L8 -> L7..L0 (atomic split-K) -> mixture -> final
// 14 launches, no reduce kernels.
// ---------------------------------------------------------------------------
extern "C" void kernel_launch(void* const* d_in, const int* in_sizes, int n_in,
                              void* d_out, int out_size) {
    const float* x     = (const float*)d_in[0];
    const float* W     = (const float*)d_in[1];
    const float* nw    = (const float*)d_in[2];
    const float* bt    = (const float*)d_in[3];
    const float* rms_w = (const float*)d_in[5];   // as_w (d_in[4]) unused (×0.0)
    float* out = (float*)d_out;

    zero_internal_kernel<<<1020, 256>>>();
    leaves_kernel<<<2048, 256>>>(x);

    // level 8: M = 1024, no split, A = leaves (no threshold), direct raw store
    tree_gemm2_kernel<<<dim3(16, 16, 1), 128>>>(W, nullptr, 8, 255, 256, 1, 2048);

    for (int lvl = 7; lvl >= 0; --lvl) {
        int NL = 1 << lvl;
        int ls = NL - 1;
        int Mtot = 4 * NL;
        int S = 1024 / Mtot; if (S > 16) S = 16;
        int Kslab = 2048 / S;
        dim3 grid((Mtot + 63) / 64, 16, S);
        // children are level lvl+1 -> threshold row bt[lvl+1]
        tree_gemm2_kernel<<<grid, 128>>>(W, bt + (size_t)(lvl + 1) * DD,
                                         lvl, ls, NL, S, Kslab);
    }

    mixture1_kernel<<<dim3(32, 8), 512>>>(nw, bt);
    mixture2_kernel<<<4, 256>>>();
    final_kernel<<<4096, 256>>>(x, rms_w, out);
}

// round 6
// speedup vs baseline: 3.7755x; 1.4013x over previous
#include <cuda_runtime.h>
#include <cstdint>
#include <cstddef>

#define NN 1023
#define DD 1024
#define BB 4
#define TT 8192
#define SST 44   // padded smem row stride (floats): float4-aligned + conflict-free frag loads

__device__ __align__(16) float g_states[BB * NN * DD];     // node states, fp32 (raw proj for internal nodes)
__device__ __align__(16) float g_mixture[BB * DD];
__device__ __align__(16) float g_mixpart[8][5][DD];        // [split][Z,a0..a3][d]

// ---------------------------------------------------------------------------
// 0+1. Prep: blk < 2048 -> leaves mean-pool; else zero internal nodes 0..510
//      (atomic split-K targets) for all batches.
// ---------------------------------------------------------------------------
__global__ void __launch_bounds__(256) prep_kernel(const float* __restrict__ x) {
    int blk = blockIdx.x;
    if (blk < 2048) {
        int b = blk >> 9;
        int l = blk & 511;
        int d4 = threadIdx.x;
        const float4* xp = reinterpret_cast<const float4*>(x)
                           + ((size_t)(b * TT + l * 8)) * 256 + d4;
        float sx = 0.f, sy = 0.f, sz = 0.f, sw = 0.f;
#pragma unroll
        for (int i = 0; i < 8; i++) {
            float4 v = xp[(size_t)i * 256];
            sx += v.x; sy += v.y; sz += v.z; sw += v.w;
        }
        float4 o;
        o.x = sx * 0.125f; o.y = sy * 0.125f; o.z = sz * 0.125f; o.w = sw * 0.125f;
        reinterpret_cast<float4*>(g_states)[((size_t)b * NN + 511 + l) * 256 + d4] = o;
    } else {
        // zero nodes 0..510, 4 batches: 4*511*1024/4 = 523264 float4
        int i = (blk - 2048) * 256 + threadIdx.x;
        if (i < 523264) {
            int b = i / 130816;               // 511*1024/4
            int r = i - b * 130816;
            reinterpret_cast<float4*>(g_states + (size_t)b * NN * DD)[r] =
                make_float4(0.f, 0.f, 0.f, 0.f);
        }
    }
}

// ---------------------------------------------------------------------------
// 2. Tree level GEMM, tf32 mma, batch folded into M, split-K via atomicAdd,
//    cp.async double-buffered, lazy spike threshold applied ONCE per A tile
//    in smem (children level L+1 thresholds bt[L+1][k&1023]); level 8 (leaves)
//    passes btc = null -> no threshold work at all.
// ---------------------------------------------------------------------------
__device__ __forceinline__ void mma_tf32(float c[4], const unsigned a[4], const unsigned b[2]) {
    asm volatile(
        "mma.sync.aligned.m16n8k8.row.col.f32.tf32.tf32.f32 "
        "{%0,%1,%2,%3}, {%4,%5,%6,%7}, {%8,%9}, {%0,%1,%2,%3};\n"
        : "+f"(c[0]), "+f"(c[1]), "+f"(c[2]), "+f"(c[3])
        : "r"(a[0]), "r"(a[1]), "r"(a[2]), "r"(a[3]),
          "r"(b[0]), "r"(b[1]));
}

__device__ __forceinline__ unsigned smem_u32(const void* p) {
    return (unsigned)__cvta_generic_to_shared(p);
}

__global__ void __launch_bounds__(128) tree_gemm2_kernel(const float* __restrict__ W,
                                                         const float* __restrict__ btc,
                                                         int level, int ls, int NL,
                                                         int Kslab) {
    int split = blockIdx.z;
    int m0 = blockIdx.x * 64;
    int n0 = blockIdx.y * 64;
    int Mtot = NL * 4;
    int kbeg = split * Kslab;
    int iters = Kslab >> 5;

    __shared__ float As[2][64 * SST];
    __shared__ float Bs[2][64 * SST];
    __shared__ float tb[2][32];          // child thresholds for this K chunk

    int tid = threadIdx.x;
    int warp = tid >> 5, lane = tid & 31;
    int wm = warp >> 1, wn = warp & 1;
    int g = lane >> 2, t4 = lane & 3;

    float acc[2][4][4];
#pragma unroll
    for (int i = 0; i < 2; i++)
#pragma unroll
        for (int j = 0; j < 4; j++)
#pragma unroll
            for (int k = 0; k < 4; k++) acc[i][j][k] = 0.f;

#define STAGE(buf, kg)                                                               \
    {                                                                                \
        _Pragma("unroll")                                                            \
        for (int q = 0; q < 4; q++) {                                                \
            int i = q * 128 + tid;                                                   \
            int r = i >> 3, c = i & 7;                                               \
            unsigned sa = smem_u32(&As[buf][r * SST + c * 4]);                       \
            int rg = m0 + r;                                                         \
            const float* pa = W;                                                     \
            int sz = 0;                                                              \
            if (rg < Mtot) {                                                         \
                int bb = rg >> level;                                                \
                int jj = rg & (NL - 1);                                              \
                pa = g_states + ((size_t)bb * NN + (2 * ls + 1) + 2 * jj) * DD       \
                     + (kg) + c * 4;                                                 \
                sz = 16;                                                             \
            }                                                                        \
            asm volatile("cp.async.cg.shared.global [%0], [%1], 16, %2;\n"           \
                         :: "r"(sa), "l"(pa), "r"(sz));                              \
            unsigned sb = smem_u32(&Bs[buf][r * SST + c * 4]);                       \
            const float* pb = W + (size_t)(n0 + r) * 2048 + (kg) + c * 4;            \
            asm volatile("cp.async.cg.shared.global [%0], [%1], 16;\n"               \
                         :: "r"(sb), "l"(pb));                                       \
        }                                                                            \
        if (btc && tid < 8) {                                                        \
            unsigned st = smem_u32(&tb[buf][tid * 4]);                               \
            const float* pt = btc + (((kg) & 1023) + tid * 4);                       \
            asm volatile("cp.async.ca.shared.global [%0], [%1], 16;\n"               \
                         :: "r"(st), "l"(pt));                                       \
        }                                                                            \
        asm volatile("cp.async.commit_group;\n");                                    \
    }

    STAGE(0, kbeg);

    for (int it = 0; it < iters; ++it) {
        int cur = it & 1;
        if (it + 1 < iters) {
            STAGE(cur ^ 1, kbeg + (it + 1) * 32);
            asm volatile("cp.async.wait_group 1;\n");
        } else {
            asm volatile("cp.async.wait_group 0;\n");
        }
        __syncthreads();

        // lazy spike threshold: one pass over the A tile in smem
        if (btc) {
#pragma unroll
            for (int q = 0; q < 4; q++) {
                int i = q * 128 + tid;
                int r = i >> 3, c = i & 7;
                float4 t = *reinterpret_cast<float4*>(&tb[cur][c * 4]);
                float4 v = *reinterpret_cast<float4*>(&As[cur][r * SST + c * 4]);
                v.x = v.x > t.x ? v.x : 0.f;
                v.y = v.y > t.y ? v.y : 0.f;
                v.z = v.z > t.z ? v.z : 0.f;
                v.w = v.w > t.w ? v.w : 0.f;
                *reinterpret_cast<float4*>(&As[cur][r * SST + c * 4]) = v;
            }
            __syncthreads();
        }

#pragma unroll
        for (int kk = 0; kk < 32; kk += 8) {
            unsigned a[2][4], bf[4][2];
#pragma unroll
            for (int i = 0; i < 2; i++) {
                int rb = (wm * 32 + i * 16 + g) * SST + kk + t4;
                a[i][0] = __float_as_uint(As[cur][rb]);
                a[i][1] = __float_as_uint(As[cur][rb + 8 * SST]);
                a[i][2] = __float_as_uint(As[cur][rb + 4]);
                a[i][3] = __float_as_uint(As[cur][rb + 8 * SST + 4]);
            }
#pragma unroll
            for (int j = 0; j < 4; j++) {
                int rb = (wn * 32 + j * 8 + g) * SST + kk + t4;
                bf[j][0] = __float_as_uint(Bs[cur][rb]);
                bf[j][1] = __float_as_uint(Bs[cur][rb + 4]);
            }
#pragma unroll
            for (int i = 0; i < 2; i++)
#pragma unroll
                for (int j = 0; j < 4; j++)
                    mma_tf32(acc[i][j], a[i], bf[j]);
        }
        __syncthreads();
    }
#undef STAGE

    // epilogue: atomic split-K accumulate of RAW proj (threshold lazy at consumers)
#pragma unroll
    for (int i = 0; i < 2; i++) {
        int rg = m0 + wm * 32 + i * 16 + g;
#pragma unroll
        for (int j = 0; j < 4; j++) {
            int col = n0 + wn * 32 + j * 8 + t4 * 2;
            if (rg < Mtot) {
                int bb = rg >> level, jj = rg & (NL - 1);
                float* Crow = g_states + ((size_t)bb * NN + ls + jj) * DD;
                atomicAdd(&Crow[col],     acc[i][j][0]);
                atomicAdd(&Crow[col + 1], acc[i][j][1]);
            }
            int rg8 = rg + 8;
            if (rg8 < Mtot) {
                int bb = rg8 >> level, jj = rg8 & (NL - 1);
                float* Crow = g_states + ((size_t)bb * NN + ls + jj) * DD;
                atomicAdd(&Crow[col],     acc[i][j][2]);
                atomicAdd(&Crow[col + 1], acc[i][j][3]);
            }
        }
    }
}

// ---------------------------------------------------------------------------
// 3. Mixture, two-stage, with lazy spike threshold per node level.
// ---------------------------------------------------------------------------
__global__ void __launch_bounds__(512) mixture1_kernel(const float* __restrict__ nw,
                                                       const float* __restrict__ bt) {
    int ld = threadIdx.x & 31;
    int ln = threadIdx.x >> 5;            // 0..15
    int d  = blockIdx.x * 32 + ld;
    int sp = blockIdx.y;                  // nodes [sp*128, sp*128+128) ∩ [0,1023)
    int nend = sp * 128 + 128;
    if (nend > NN) nend = NN;
    float Z = 0.f, a0 = 0.f, a1 = 0.f, a2 = 0.f, a3 = 0.f;
    for (int n = sp * 128 + ln; n < nend; n += 16) {
        float e = __expf(nw[n * DD + d]);
        float v0 = g_states[((size_t)0 * NN + n) * DD + d];
        float v1 = g_states[((size_t)1 * NN + n) * DD + d];
        float v2 = g_states[((size_t)2 * NN + n) * DD + d];
        float v3 = g_states[((size_t)3 * NN + n) * DD + d];
        if (n < 511) {
            int lv = 31 - __clz(n + 1);
            float thr = bt[lv * DD + d];
            v0 = v0 > thr ? v0 : 0.f;
            v1 = v1 > thr ? v1 : 0.f;
            v2 = v2 > thr ? v2 : 0.f;
            v3 = v3 > thr ? v3 : 0.f;
        }
        Z += e;
        a0 += e * v0; a1 += e * v1; a2 += e * v2; a3 += e * v3;
    }
    __shared__ float red[5][16][32];
    red[0][ln][ld] = Z;  red[1][ln][ld] = a0; red[2][ln][ld] = a1;
    red[3][ln][ld] = a2; red[4][ln][ld] = a3;
    __syncthreads();
    if (ln == 0) {
        float v[5];
#pragma unroll
        for (int k = 0; k < 5; k++) {
            float s = 0.f;
#pragma unroll
            for (int i = 0; i < 16; i++) s += red[k][i][ld];
            v[k] = s;
        }
#pragma unroll
        for (int k = 0; k < 5; k++) g_mixpart[sp][k][d] = v[k];
    }
}

__global__ void __launch_bounds__(256) mixture2_kernel() {
    int d = blockIdx.x * 256 + threadIdx.x;   // grid 4
    float Z = 0.f, a0 = 0.f, a1 = 0.f, a2 = 0.f, a3 = 0.f;
#pragma unroll
    for (int sp = 0; sp < 8; sp++) {
        Z  += g_mixpart[sp][0][d];
        a0 += g_mixpart[sp][1][d];
        a1 += g_mixpart[sp][2][d];
        a2 += g_mixpart[sp][3][d];
        a3 += g_mixpart[sp][4][d];
    }
    float inv = 1.f / Z;
    g_mixture[0 * DD + d] = a0 * inv;
    g_mixture[1 * DD + d] = a1 * inv;
    g_mixture[2 * DD + d] = a2 * inv;
    g_mixture[3 * DD + d] = a3 * inv;
}

// ---------------------------------------------------------------------------
// 4. Final: out = RMSNorm(x + mixture[b]) * rms_w, 8 rows per block.
// ---------------------------------------------------------------------------
__global__ void __launch_bounds__(256) final_kernel(const float* __restrict__ x,
                                                    const float* __restrict__ rms_w,
                                                    float* __restrict__ out) {
    int blk = blockIdx.x;                 // 4096 blocks
    int b  = blk >> 10;
    int t0 = (blk & 1023) * 8;
    int tid = threadIdx.x;
    int lane = tid & 31, warp = tid >> 5;

    __shared__ float4 smix[256];
    __shared__ float4 srw[256];
    __shared__ float  sred[8];

    smix[tid] = reinterpret_cast<const float4*>(g_mixture + b * DD)[tid];
    srw[tid]  = reinterpret_cast<const float4*>(rms_w)[tid];
    __syncthreads();
    float4 mix = smix[tid], rw = srw[tid];

    const float4* xb = reinterpret_cast<const float4*>(x)   + ((size_t)(b * TT + t0)) * 256;
    float4*       ob = reinterpret_cast<float4*>(out)       + ((size_t)(b * TT + t0)) * 256;

    for (int r = 0; r < 8; r++) {
        float4 v = xb[(size_t)r * 256 + tid];
        v.x += mix.x; v.y += mix.y; v.z += mix.z; v.w += mix.w;
        float ss = v.x * v.x + v.y * v.y + v.z * v.z + v.w * v.w;
#pragma unroll
        for (int o = 16; o > 0; o >>= 1) ss += __shfl_xor_sync(0xffffffffu, ss, o);
        __syncthreads();
        if (lane == 0) sred[warp] = ss;
        __syncthreads();
        float tot = 0.f;
#pragma unroll
        for (int i = 0; i < 8; i++) tot += sred[i];
        float inv = rsqrtf(tot * (1.0f / 1024.0f) + 1.1920929e-7f);
        float4 o4;
        o4.x = v.x * rw.x * inv; o4.y = v.y * rw.y * inv;
        o4.z = v.z * rw.z * inv; o4.w = v.w * rw.w * inv;
        ob[(size_t)r * 256 + tid] = o4;
    }
}

// ---------------------------------------------------------------------------
// launch: prep -> L8..L0 (atomic split-K, occupancy-sized S) -> mixture -> final
// 13 launches.
// ---------------------------------------------------------------------------
extern "C" void kernel_launch(void* const* d_in, const int* in_sizes, int n_in,
                              void* d_out, int out_size) {
    const float* x     = (const float*)d_in[0];
    const float* W     = (const float*)d_in[1];
    const float* nw    = (const float*)d_in[2];
    const float* bt    = (const float*)d_in[3];
    const float* rms_w = (const float*)d_in[5];   // as_w (d_in[4]) unused (×0.0)
    float* out = (float*)d_out;

    prep_kernel<<<4092, 256>>>(x);    // leaves (2048) + zero nodes 0..510 (2044)

    for (int lvl = 8; lvl >= 0; --lvl) {
        int NL = 1 << lvl;
        int ls = NL - 1;
        int Mtot = 4 * NL;
        int S = 4096 / Mtot; if (S > 16) S = 16;   // L8:4 L7:8 L6..L0:16
        int Kslab = 2048 / S;
        dim3 grid((Mtot + 63) / 64, 16, S);
        const float* btc = (lvl == 8) ? nullptr : (bt + (size_t)(lvl + 1) * DD);
        tree_gemm2_kernel<<<grid, 128>>>(W, btc, lvl, ls, NL, Kslab);
    }

    mixture1_kernel<<<dim3(32, 8), 512>>>(nw, bt);
    mixture2_kernel<<<4, 256>>>();
    final_kernel<<<4096, 256>>>(x, rms_w, out);
}